// round 3
// baseline (speedup 1.0000x reference)
#include <cuda_runtime.h>
#include <cuda_fp16.h>
#include <cstdint>

#define NROWS 8192
#define DIN   512
#define DOUT  512

// ---------------- scratch (device globals; allocation is forbidden) ----------------
__device__ __half g_ba[(size_t)NROWS * DIN];      // binarized activations {0,1}   [8192,512]
__device__ __half g_bwT[(size_t)DIN * DOUT];      // sign(W)^T  {-1,0,1}           [512,512] (k-major)
__device__ __half g_xw[(size_t)NROWS * DOUT];     // xw fp16                       [8192,512]
__device__ __half g_supp[(size_t)NROWS * NROWS];  // support fp16                  [8192,8192]

// ---------------- small helpers ----------------
__device__ __forceinline__ uint32_t smem_u32(const void* p) {
    uint32_t a;
    asm("{ .reg .u64 t; cvta.to.shared.u64 t, %1; cvt.u32.u64 %0, t; }" : "=r"(a) : "l"(p));
    return a;
}

__device__ __forceinline__ void cp_async16(uint32_t dst, const void* src) {
    asm volatile("cp.async.cg.shared.global [%0], [%1], 16;\n" :: "r"(dst), "l"(src));
}
#define CP_COMMIT() asm volatile("cp.async.commit_group;\n" ::: "memory")
#define CP_WAIT1()  asm volatile("cp.async.wait_group 1;\n" ::: "memory")

__device__ __forceinline__ void ldsm_x4(uint32_t* r, uint32_t addr) {
    asm volatile("ldmatrix.sync.aligned.m8n8.x4.shared.b16 {%0,%1,%2,%3}, [%4];"
                 : "=r"(r[0]), "=r"(r[1]), "=r"(r[2]), "=r"(r[3]) : "r"(addr));
}
__device__ __forceinline__ void ldsm_x4_t(uint32_t* r, uint32_t addr) {
    asm volatile("ldmatrix.sync.aligned.m8n8.x4.trans.shared.b16 {%0,%1,%2,%3}, [%4];"
                 : "=r"(r[0]), "=r"(r[1]), "=r"(r[2]), "=r"(r[3]) : "r"(addr));
}
__device__ __forceinline__ void mma16816(float* c, const uint32_t* a, const uint32_t* b) {
    asm volatile(
        "mma.sync.aligned.m16n8k16.row.col.f32.f16.f16.f32 "
        "{%0,%1,%2,%3}, {%4,%5,%6,%7}, {%8,%9}, {%0,%1,%2,%3};"
        : "+f"(c[0]), "+f"(c[1]), "+f"(c[2]), "+f"(c[3])
        : "r"(a[0]), "r"(a[1]), "r"(a[2]), "r"(a[3]), "r"(b[0]), "r"(b[1]));
}

// epilogue store: float => relu, half => raw convert
__device__ __forceinline__ void store2(float* dst, float a, float b) {
    float2 v; v.x = fmaxf(a, 0.f); v.y = fmaxf(b, 0.f);
    *reinterpret_cast<float2*>(dst) = v;
}
__device__ __forceinline__ void store2(__half* dst, float a, float b) {
    *reinterpret_cast<__half2*>(dst) = __floats2half2_rn(a, b);
}

// ---------------- GEMM: C[m,n] = op( sum_k A[m,k] * B[k,n] ) ----------------
// A row-major [M,K] fp16, B row-major [K,N] fp16. Tiles BM=128, BN=256, BK=64.
// 8 warps = 2(m) x 4(n), warp tile 64x64. 3-stage cp.async pipeline.
#define BM 128
#define BN 256
#define BK 64
#define STG 3
#define A_BYTES (BM * BK * 2)           // 16384
#define B_BYTES (BK * BN * 2)           // 32768
#define STG_BYTES (A_BYTES + B_BYTES)   // 49152
#define SMEM_DYN (1024 + STG * STG_BYTES)

// swizzles: A rows 128B, B rows 512B
#define SWZA(o) ((o) ^ (((o) >> 3) & 0x70))
#define SWZB(o) ((o) ^ (((o) >> 5) & 0x70))

template <typename OutT>
__global__ void __launch_bounds__(256, 1)
gemm_hmma(const __half* __restrict__ A, const __half* __restrict__ B, OutT* __restrict__ C,
          int lda, int ldb, int ldc, int K) {
    extern __shared__ char smem_raw[];
    const int tid = threadIdx.x;
    const int wid = tid >> 5;
    const int lid = tid & 31;
    const int warpM = wid >> 2;          // 0..1
    const int warpN = wid & 3;           // 0..3
    const int bm = blockIdx.y, bn = blockIdx.x;

    uint32_t sbase = (smem_u32(smem_raw) + 1023u) & ~1023u;

    const __half* Abase = A + (size_t)bm * BM * lda;
    const __half* Bbase = B + (size_t)bn * BN;

    auto load_stage = [&](int s, int k0) {
        uint32_t sA = sbase + (uint32_t)s * STG_BYTES;
        uint32_t sB = sA + A_BYTES;
        // A: 1024 chunks of 16B (128 rows x 8 chunks)
#pragma unroll
        for (int i = 0; i < 4; i++) {
            int c = tid + i * 256;
            int r = c >> 3, q = c & 7;
            cp_async16(sA + SWZA((uint32_t)(r * 128 + q * 16)),
                       Abase + (size_t)r * lda + k0 + q * 8);
        }
        // B: 2048 chunks (64 rows x 32 chunks)
#pragma unroll
        for (int i = 0; i < 8; i++) {
            int c = tid + i * 256;
            int r = c >> 5, q = c & 31;
            cp_async16(sB + SWZB((uint32_t)(r * 512 + q * 16)),
                       Bbase + (size_t)(k0 + r) * ldb + q * 8);
        }
    };

    const int NK = K / BK;

    load_stage(0, 0);  CP_COMMIT();
    load_stage(1, BK); CP_COMMIT();

    float acc[4][8][4];
#pragma unroll
    for (int mi = 0; mi < 4; mi++)
#pragma unroll
        for (int nj = 0; nj < 8; nj++)
#pragma unroll
            for (int f = 0; f < 4; f++) acc[mi][nj][f] = 0.f;

    // per-thread constant address pieces
    const uint32_t axor = (uint32_t)(lid & 7) << 4;
    const uint32_t bxor = axor;
    uint32_t aRow[4];
#pragma unroll
    for (int mi = 0; mi < 4; mi++)
        aRow[mi] = (uint32_t)((warpM * 64 + mi * 16 + (lid & 15)) * 128);
    const uint32_t aHi = (uint32_t)((lid >> 4) * 16);
    uint32_t bCol[4];
#pragma unroll
    for (int p = 0; p < 4; p++)
        bCol[p] = ((uint32_t)(warpN * 128 + p * 32 + (lid >> 4) * 16)) ^ bxor;
    const uint32_t bRow = (uint32_t)((lid & 15) * 512);

    for (int ks = 0; ks < NK; ks++) {
        CP_WAIT1();
        __syncthreads();
        // prefetch two stages ahead into the slot freed last iteration
        int kn = ks + 2;
        if (kn < NK) {
            load_stage(kn % STG, kn * BK);
            CP_COMMIT();
        }
        uint32_t sA = sbase + (uint32_t)(ks % STG) * STG_BYTES;
        uint32_t sB = sA + A_BYTES;
#pragma unroll
        for (int kk = 0; kk < 4; kk++) {
            uint32_t afr[4][4], bfr[4][4];
            const uint32_t aColS = ((uint32_t)(kk * 32) + aHi) ^ axor;
#pragma unroll
            for (int mi = 0; mi < 4; mi++)
                ldsm_x4(afr[mi], sA + aRow[mi] + aColS);
            const uint32_t bRowS = sB + (uint32_t)(kk * 16 * 512) + bRow;
#pragma unroll
            for (int p = 0; p < 4; p++)
                ldsm_x4_t(bfr[p], bRowS + bCol[p]);
#pragma unroll
            for (int mi = 0; mi < 4; mi++)
#pragma unroll
                for (int p = 0; p < 4; p++) {
                    mma16816(acc[mi][2 * p],     afr[mi], &bfr[p][0]);
                    mma16816(acc[mi][2 * p + 1], afr[mi], &bfr[p][2]);
                }
        }
    }

    // epilogue: direct global stores
    const int g = lid >> 2, tg = lid & 3;
    const int rowBase = bm * BM + warpM * 64;
    const int colBase = bn * BN + warpN * 64;
#pragma unroll
    for (int mi = 0; mi < 4; mi++) {
        int r0 = rowBase + mi * 16 + g;
        OutT* p0 = C + (size_t)r0 * ldc + colBase;
        OutT* p1 = p0 + (size_t)8 * ldc;
#pragma unroll
        for (int nj = 0; nj < 8; nj++) {
            int c = nj * 8 + tg * 2;
            store2(p0 + c, acc[mi][nj][0], acc[mi][nj][1]);
            store2(p1 + c, acc[mi][nj][2], acc[mi][nj][3]);
        }
    }
}

// ---------------- elementwise kernels ----------------
__global__ void k_bin_x(const float4* __restrict__ in, __half* __restrict__ out, int n4) {
    int i = blockIdx.x * blockDim.x + threadIdx.x;
    int strd = gridDim.x * blockDim.x;
    for (; i < n4; i += strd) {
        float4 v = in[i];
        __half2 a = __floats2half2_rn(v.x > 0.f ? 1.f : 0.f, v.y > 0.f ? 1.f : 0.f);
        __half2 b = __floats2half2_rn(v.z > 0.f ? 1.f : 0.f, v.w > 0.f ? 1.f : 0.f);
        union { __half2 h[2]; uint2 u; } cv; cv.h[0] = a; cv.h[1] = b;
        reinterpret_cast<uint2*>(out)[i] = cv.u;
    }
}

__device__ __forceinline__ float fsign(float v) {
    return (v > 0.f) ? 1.f : ((v < 0.f) ? -1.f : 0.f);
}

// transpose + binarize: bwT[k, j] = sign(w[j, k]); 32x32 smem tiles
__global__ void k_bin_wT(const float* __restrict__ w, __half* __restrict__ bwT) {
    __shared__ float t[32][33];
    int j0 = blockIdx.y * 32, k0 = blockIdx.x * 32;
    int tx = threadIdx.x, ty = threadIdx.y;
    // read w rows coalesced
    for (int r = ty; r < 32; r += 8)
        t[r][tx] = w[(size_t)(j0 + r) * DIN + k0 + tx];
    __syncthreads();
    for (int r = ty; r < 32; r += 8)
        bwT[(size_t)(k0 + r) * DOUT + j0 + tx] = __float2half_rn(fsign(t[tx][r]));
}

__global__ void k_cvt_half(const float4* __restrict__ in, __half* __restrict__ out, int n4) {
    int i = blockIdx.x * blockDim.x + threadIdx.x;
    int strd = gridDim.x * blockDim.x;
    for (; i < n4; i += strd) {
        float4 v = in[i];
        __half2 a = __floats2half2_rn(v.x, v.y);
        __half2 b = __floats2half2_rn(v.z, v.w);
        union { __half2 h[2]; uint2 u; } cv; cv.h[0] = a; cv.h[1] = b;
        reinterpret_cast<uint2*>(out)[i] = cv.u;
    }
}

// ---------------- launch ----------------
extern "C" void kernel_launch(void* const* d_in, const int* in_sizes, int n_in,
                              void* d_out, int out_size) {
    const float *x = nullptr, *supp = nullptr, *w = nullptr;
    for (int i = 0; i < n_in; i++) {
        if (in_sizes[i] == NROWS * DIN)       x    = (const float*)d_in[i];
        else if (in_sizes[i] == DOUT * DIN)   w    = (const float*)d_in[i];
        else                                  supp = (const float*)d_in[i];  // 8192*8192
    }

    __half *ba, *bwT, *xw, *sh;
    cudaGetSymbolAddress((void**)&ba,  g_ba);
    cudaGetSymbolAddress((void**)&bwT, g_bwT);
    cudaGetSymbolAddress((void**)&xw,  g_xw);
    cudaGetSymbolAddress((void**)&sh,  g_supp);

    cudaFuncSetAttribute(gemm_hmma<__half>, cudaFuncAttributeMaxDynamicSharedMemorySize, SMEM_DYN);
    cudaFuncSetAttribute(gemm_hmma<float>,  cudaFuncAttributeMaxDynamicSharedMemorySize, SMEM_DYN);

    // binarize activations and weights, then GEMM1 (independent of support conversion)
    k_bin_x<<<4096, 256>>>((const float4*)x, ba, (NROWS * DIN) / 4);
    k_bin_wT<<<dim3(16, 16), dim3(32, 8)>>>(w, bwT);

    // GEMM1: xw[i,j] = sum_d ba[i,d] * bwT[d,j]      (M=8192, N=512, K=512)
    gemm_hmma<__half><<<dim3(DOUT / BN, NROWS / BM), 256, SMEM_DYN>>>(
        ba, bwT, xw, DIN, DOUT, DOUT, DIN);

    // support fp32 -> fp16 (largest; HBM-bound)
    k_cvt_half<<<8192, 256>>>((const float4*)supp, sh, (int)(((size_t)NROWS * NROWS) / 4));

    // GEMM2: out[m,n] = relu(sum_k supp[m,k] * xw[k,n])  (M=8192, N=512, K=8192)
    gemm_hmma<float><<<dim3(DOUT / BN, NROWS / BM), 256, SMEM_DYN>>>(
        sh, xw, (float*)d_out, NROWS, DOUT, DOUT, NROWS);
}